// round 14
// baseline (speedup 1.0000x reference)
#include <cuda_runtime.h>
#include <math.h>

#define UNITS 1024
#define FEAT  1024
#define GCOLS 4096                  // 4 * UNITS gate columns
#define CTILE 512                   // scalar columns per block (2KB rows)
#define C4T   (CTILE / 4)           // 128 float4 cols per block
#define NCB   (GCOLS / CTILE)       // 8 column tiles
#define KS    16                    // k-slices
#define KROWS (FEAT / KS)           // 64 k-rows per block
#define KTG   8                     // kt groups (1024 threads / 128 cols)
#define KPT   (KROWS / KTG)         // 8 k-rows per thread

#define TILE_BYTES (KROWS * CTILE * 4)   // 131072 B
#define ROW_BYTES  (CTILE * 4)           // 2048 B contiguous per k-row

// dynamic smem layout
#define OFF_MBAR  0
#define OFF_TILE  1024
#define OFF_XS0   (OFF_TILE + TILE_BYTES)
#define OFF_XS1   (OFF_XS0 + KROWS * 4)
#define OFF_SRED0 (OFF_XS1 + KROWS * 4)
#define OFF_SRED1 (OFF_SRED0 + KTG * C4T * 16)
#define SMEM_XW   (OFF_SRED1 + KTG * C4T * 16)
#define OFF_H0S   (OFF_TILE + TILE_BYTES)
#define OFF_SREDU (OFF_H0S + KROWS * 4)
#define SMEM_HU   (OFF_SREDU + KTG * C4T * 16)

// Scratch (device globals)
__device__ float4 g_p0[KS][GCOLS / 4];   // partials of x0@W
__device__ float4 g_p1[KS][GCOLS / 4];   // partials of x1@W
__device__ float4 g_pu[KS][GCOLS / 4];   // partials of h0@U

__device__ __forceinline__ float sigmoidf_(float x) {
    return 1.0f / (1.0f + expf(-x));
}
__device__ __forceinline__ unsigned smem_u32(const void* p) {
    return (unsigned)__cvta_generic_to_shared(p);
}
__device__ __forceinline__ void mbar_init(unsigned mbar, unsigned count) {
    asm volatile("mbarrier.init.shared.b64 [%0], %1;" :: "r"(mbar), "r"(count) : "memory");
}
__device__ __forceinline__ void mbar_expect_tx(unsigned mbar, unsigned bytes) {
    asm volatile("mbarrier.arrive.expect_tx.shared.b64 _, [%0], %1;"
                 :: "r"(mbar), "r"(bytes) : "memory");
}
__device__ __forceinline__ void mbar_wait(unsigned mbar, unsigned parity) {
    asm volatile(
        "{\n\t"
        ".reg .pred P1;\n\t"
        "WAIT_LOOP_%=:\n\t"
        "mbarrier.try_wait.parity.acquire.cta.shared::cta.b64 P1, [%0], %1, 0x989680;\n\t"
        "@P1 bra.uni WAIT_DONE_%=;\n\t"
        "bra.uni WAIT_LOOP_%=;\n\t"
        "WAIT_DONE_%=:\n\t"
        "}"
        :: "r"(mbar), "r"(parity) : "memory");
}
__device__ __forceinline__ void bulk_g2s(unsigned sdst, const void* gsrc,
                                         unsigned bytes, unsigned mbar) {
    asm volatile(
        "cp.async.bulk.shared::cluster.global.mbarrier::complete_tx::bytes "
        "[%0], [%1], %2, [%3];"
        :: "r"(sdst), "l"(gsrc), "r"(bytes), "r"(mbar) : "memory");
}

// Fold the KS partials of a scalar gate column (fixed order).
__device__ __forceinline__ float fold_p(const float4 (*p)[GCOLS / 4], int col) {
    const float* base = reinterpret_cast<const float*>(p);
    float s = 0.f;
    #pragma unroll
    for (int sI = 0; sI < KS; ++sI) s += base[sI * GCOLS + col];
    return s;
}

// ---------------------------------------------------------------------------
// Kernel 1: partial GEMV over W for t=0 and t=1.
// grid = (NCB, KS) = (8, 16) = 128 blocks x 1024 threads.
// Block (cb, ks): cols [cb*512, +512), k-rows [ks*64, +64).
// TMA fill: 64 bulk copies of one contiguous 2KB k-row each.
// Consume: thread (c4 = tid&127, kt = tid>>7) accumulates 8 k-rows;
// warp reads 512B contiguous per row -> conflict-free. 8-way smem fold.
// ---------------------------------------------------------------------------
__global__ void __launch_bounds__(1024, 1)
k_xw(const float* __restrict__ x, const float* __restrict__ W) {
    extern __shared__ char dyn[];
    float*  Wt   = (float*)(dyn + OFF_TILE);    // [KROWS][CTILE]
    float*  xs0  = (float*)(dyn + OFF_XS0);
    float*  xs1  = (float*)(dyn + OFF_XS1);
    float4* sred0 = (float4*)(dyn + OFF_SRED0); // [KTG][C4T]
    float4* sred1 = (float4*)(dyn + OFF_SRED1);
    const unsigned mbar = smem_u32(dyn + OFF_MBAR);

    const int tid = threadIdx.x;
    const int c4  = tid & (C4T - 1);
    const int kt  = tid >> 7;
    const int cb  = blockIdx.x;
    const int ks  = blockIdx.y;
    const int kbase = ks * KROWS;

    if (tid == 0) {
        mbar_init(mbar, 1);
        mbar_expect_tx(mbar, TILE_BYTES);
    }
    __syncthreads();

    const char* gW = (const char*)(W + (size_t)kbase * GCOLS + cb * CTILE);
    if (tid < KROWS) {
        bulk_g2s(smem_u32(Wt + tid * CTILE), gW + (size_t)tid * (GCOLS * 4),
                 ROW_BYTES, mbar);
    }
    for (int i = tid; i < KROWS; i += 1024) {
        xs0[i] = x[kbase + i];
        xs1[i] = x[FEAT + kbase + i];
    }
    __syncthreads();
    mbar_wait(mbar, 0);

    float4 a0 = make_float4(0.f, 0.f, 0.f, 0.f);
    float4 a1 = make_float4(0.f, 0.f, 0.f, 0.f);
    #pragma unroll
    for (int kk = 0; kk < KPT; ++kk) {
        const int row = kt * KPT + kk;
        const float4 w = reinterpret_cast<const float4*>(Wt + row * CTILE)[c4];
        const float xa = xs0[row];
        const float xb = xs1[row];
        a0.x = fmaf(xa, w.x, a0.x); a0.y = fmaf(xa, w.y, a0.y);
        a0.z = fmaf(xa, w.z, a0.z); a0.w = fmaf(xa, w.w, a0.w);
        a1.x = fmaf(xb, w.x, a1.x); a1.y = fmaf(xb, w.y, a1.y);
        a1.z = fmaf(xb, w.z, a1.z); a1.w = fmaf(xb, w.w, a1.w);
    }
    sred0[kt * C4T + c4] = a0;
    sred1[kt * C4T + c4] = a1;
    __syncthreads();

    if (tid < C4T) {
        float4 s0 = make_float4(0.f, 0.f, 0.f, 0.f);
        float4 s1 = make_float4(0.f, 0.f, 0.f, 0.f);
        #pragma unroll
        for (int j = 0; j < KTG; ++j) {
            const float4 v0 = sred0[j * C4T + tid];
            const float4 v1 = sred1[j * C4T + tid];
            s0.x += v0.x; s0.y += v0.y; s0.z += v0.z; s0.w += v0.w;
            s1.x += v1.x; s1.y += v1.y; s1.z += v1.z; s1.w += v1.w;
        }
        g_p0[ks][cb * C4T + tid] = s0;
        g_p1[ks][cb * C4T + tid] = s1;
    }
}

// ---------------------------------------------------------------------------
// Kernel 2: partial GEMV over U. Same TMA tiling; the h0 values for this
// block's 64 k-rows are folded from g_p0 (+b) while the tile streams in.
// ---------------------------------------------------------------------------
__global__ void __launch_bounds__(1024, 1)
k_hu(const float* __restrict__ U, const float* __restrict__ b) {
    extern __shared__ char dyn[];
    float*  Ut   = (float*)(dyn + OFF_TILE);
    float*  h0s  = (float*)(dyn + OFF_H0S);
    float4* sred = (float4*)(dyn + OFF_SREDU);
    const unsigned mbar = smem_u32(dyn + OFF_MBAR);

    const int tid = threadIdx.x;
    const int c4  = tid & (C4T - 1);
    const int kt  = tid >> 7;
    const int cb  = blockIdx.x;
    const int ks  = blockIdx.y;
    const int kbase = ks * KROWS;

    if (tid == 0) {
        mbar_init(mbar, 1);
        mbar_expect_tx(mbar, TILE_BYTES);
    }
    __syncthreads();

    const char* gU = (const char*)(U + (size_t)kbase * GCOLS + cb * CTILE);
    if (tid < KROWS) {
        bulk_g2s(smem_u32(Ut + tid * CTILE), gU + (size_t)tid * (GCOLS * 4),
                 ROW_BYTES, mbar);
    }
    // h0 for this block's k-rows (c_prev = 0), overlapped with the TMA fill
    if (tid < KROWS) {
        const int u = kbase + tid;
        const float zi = fold_p(g_p0, u)             + __ldg(b + u);
        const float zg = fold_p(g_p0, 2 * UNITS + u) + __ldg(b + 2 * UNITS + u);
        const float zo = fold_p(g_p0, 3 * UNITS + u) + __ldg(b + 3 * UNITS + u);
        const float c0 = sigmoidf_(zi) * zg;
        h0s[tid] = sigmoidf_(zo) * c0;
    }
    __syncthreads();
    mbar_wait(mbar, 0);

    float4 a = make_float4(0.f, 0.f, 0.f, 0.f);
    #pragma unroll
    for (int kk = 0; kk < KPT; ++kk) {
        const int row = kt * KPT + kk;
        const float4 w = reinterpret_cast<const float4*>(Ut + row * CTILE)[c4];
        const float h = h0s[row];
        a.x = fmaf(h, w.x, a.x); a.y = fmaf(h, w.y, a.y);
        a.z = fmaf(h, w.z, a.z); a.w = fmaf(h, w.w, a.w);
    }
    sred[kt * C4T + c4] = a;
    __syncthreads();

    if (tid < C4T) {
        float4 s = make_float4(0.f, 0.f, 0.f, 0.f);
        #pragma unroll
        for (int j = 0; j < KTG; ++j) {
            const float4 v = sred[j * C4T + tid];
            s.x += v.x; s.y += v.y; s.z += v.z; s.w += v.w;
        }
        g_pu[ks][cb * C4T + tid] = s;
    }
}

// ---------------------------------------------------------------------------
// Kernel 3: one block, 1024 threads = UNITS. Fold partials, gate math t0/t1,
// dense head via deterministic in-block reduction, finite diff, 4 outputs.
// ---------------------------------------------------------------------------
__global__ void k_final(const float* __restrict__ f,
                        const float* __restrict__ b,
                        const float* __restrict__ Wd,
                        const float* __restrict__ bd,
                        float* __restrict__ out) {
    __shared__ float red[4][32];
    const int u = threadIdx.x;

    const float zi0 = fold_p(g_p0, u)             + __ldg(b + u);
    const float zg0 = fold_p(g_p0, 2 * UNITS + u) + __ldg(b + 2 * UNITS + u);
    const float zo0 = fold_p(g_p0, 3 * UNITS + u) + __ldg(b + 3 * UNITS + u);
    const float c0  = sigmoidf_(zi0) * zg0;
    const float h0  = sigmoidf_(zo0) * c0;

    const float zi1 = fold_p(g_p1, u)             + fold_p(g_pu, u)             + __ldg(b + u);
    const float zf1 = fold_p(g_p1, UNITS + u)     + fold_p(g_pu, UNITS + u)     + __ldg(b + UNITS + u);
    const float zg1 = fold_p(g_p1, 2 * UNITS + u) + fold_p(g_pu, 2 * UNITS + u) + __ldg(b + 2 * UNITS + u);
    const float zo1 = fold_p(g_p1, 3 * UNITS + u) + fold_p(g_pu, 3 * UNITS + u) + __ldg(b + 3 * UNITS + u);
    const float c1  = sigmoidf_(zf1) * c0 + sigmoidf_(zi1) * zg1;
    const float h1  = sigmoidf_(zo1) * c1;

    const float n0 = tanhf(h0);
    const float n1 = tanhf(h1);

    const float wd0 = __ldg(Wd + 2 * u);
    const float wd1 = __ldg(Wd + 2 * u + 1);
    float v0 = n0 * wd0;
    float v1 = n0 * wd1;
    float v2 = n1 * wd0;
    float v3 = n1 * wd1;

    const unsigned m = 0xffffffffu;
    const int lane = u & 31;
    const int wrp  = u >> 5;
    #pragma unroll
    for (int off = 16; off > 0; off >>= 1) {
        v0 += __shfl_down_sync(m, v0, off);
        v1 += __shfl_down_sync(m, v1, off);
        v2 += __shfl_down_sync(m, v2, off);
        v3 += __shfl_down_sync(m, v3, off);
    }
    if (lane == 0) {
        red[0][wrp] = v0; red[1][wrp] = v1; red[2][wrp] = v2; red[3][wrp] = v3;
    }
    __syncthreads();

    if (wrp == 0) {
        float r0 = red[0][lane];
        float r1 = red[1][lane];
        float r2 = red[2][lane];
        float r3 = red[3][lane];
        #pragma unroll
        for (int off = 16; off > 0; off >>= 1) {
            r0 += __shfl_down_sync(m, r0, off);
            r1 += __shfl_down_sync(m, r1, off);
            r2 += __shfl_down_sync(m, r2, off);
            r3 += __shfl_down_sync(m, r3, off);
        }
        if (lane == 0) {
            const float b0 = __ldg(bd + 0);
            const float b1 = __ldg(bd + 1);
            const float hc00 = tanhf(r0 + b0);
            const float hc01 = tanhf(r1 + b1);
            const float hc10 = tanhf(r2 + b0);
            const float hc11 = tanhf(r3 + b1);
            const float den  = __ldg(f + 1) - __ldg(f + 2);
            out[0] = hc00;
            out[1] = hc01;
            out[2] = (hc00 - hc10) / den;
            out[3] = (hc01 - hc11) / den;
        }
    }
}

// ---------------------------------------------------------------------------
extern "C" void kernel_launch(void* const* d_in, const int* in_sizes, int n_in,
                              void* d_out, int out_size) {
    (void)in_sizes; (void)n_in; (void)out_size;
    const float* x  = (const float*)d_in[0];
    const float* f  = (const float*)d_in[1];
    const float* W  = (const float*)d_in[2];
    const float* U  = (const float*)d_in[3];
    const float* b  = (const float*)d_in[4];
    const float* Wd = (const float*)d_in[5];
    const float* bd = (const float*)d_in[6];
    float* out = (float*)d_out;

    cudaFuncSetAttribute(k_xw, cudaFuncAttributeMaxDynamicSharedMemorySize, SMEM_XW);
    cudaFuncSetAttribute(k_hu, cudaFuncAttributeMaxDynamicSharedMemorySize, SMEM_HU);

    dim3 grid(NCB, KS);   // (8, 16) = 128 blocks
    k_xw   <<<grid, 1024, SMEM_XW>>>(x, W);
    k_hu   <<<grid, 1024, SMEM_HU>>>(U, b);
    k_final<<<1, 1024>>>(f, b, Wd, bd, out);
}